// round 15
// baseline (speedup 1.0000x reference)
#include <cuda_runtime.h>
#include <cuda_fp16.h>
#include <math.h>
#include <cstdint>

#define BB 16
#define SS 1024
#define DD 768
#define DFFN 3072
#define MTOT (BB*SS)   // 16384
#define MHALF (MTOT/2) // 8192
#define BH (BB/2)      // 8

// ---------------------------------------------------------------------------
// Static scratch (no runtime device-memory allocation)
// ---------------------------------------------------------------------------
__device__ __align__(128) __half g_srch[MTOT*DD];
__device__ __align__(128) __half g_wqkvh[3*DD*DD];             // [wq^T ; wk^T ; wv^T]
__device__ __align__(128) __half g_w1h[DD*DFFN], g_w2h[DD*DFFN];
__device__ __align__(128) __half g_qh[MTOT*DD], g_kh[MTOT*DD];
__device__ __align__(128) __half g_vh[MTOT*DD];                // v fp16 [S,D]
__device__ __align__(128) float  g_v[MTOT*DD];                 // attn_out fp32
__device__ __align__(128) __half g_vth[MTOT*DD];               // v^T per batch
__device__ __align__(128) float  g_scores[(size_t)BB*SS*SS];   // scores fp32; halves reused as ff
__device__ __align__(128) __half g_ah[(size_t)BB*SS*SS];
__device__ __align__(128) float  g_x[MTOT*DD];
__device__ __align__(128) __half g_xh[MTOT*DD];
__device__ __align__(128) __half g_hh[(size_t)MTOT*DFFN];

// ---------------------------------------------------------------------------
// streams/events: created once at static-init (host objects, pre-checkpoint)
// ---------------------------------------------------------------------------
static cudaStream_t g_s1, g_s2, g_s3, g_s4, g_s5;
static cudaEvent_t  g_eRoot, g_eC1, g_eW, g_eQ1, g_eQ2,
                    g_eV1, g_eV2, g_eW12, g_eD1, g_eD2;
static struct StreamInit {
    StreamInit() {
        cudaStreamCreateWithFlags(&g_s1, cudaStreamNonBlocking);
        cudaStreamCreateWithFlags(&g_s2, cudaStreamNonBlocking);
        cudaStreamCreateWithFlags(&g_s3, cudaStreamNonBlocking);
        cudaStreamCreateWithFlags(&g_s4, cudaStreamNonBlocking);
        cudaStreamCreateWithFlags(&g_s5, cudaStreamNonBlocking);
        cudaEventCreateWithFlags(&g_eRoot, cudaEventDisableTiming);
        cudaEventCreateWithFlags(&g_eC1,  cudaEventDisableTiming);
        cudaEventCreateWithFlags(&g_eW,   cudaEventDisableTiming);
        cudaEventCreateWithFlags(&g_eQ1,  cudaEventDisableTiming);
        cudaEventCreateWithFlags(&g_eQ2,  cudaEventDisableTiming);
        cudaEventCreateWithFlags(&g_eV1,  cudaEventDisableTiming);
        cudaEventCreateWithFlags(&g_eV2,  cudaEventDisableTiming);
        cudaEventCreateWithFlags(&g_eW12, cudaEventDisableTiming);
        cudaEventCreateWithFlags(&g_eD1,  cudaEventDisableTiming);
        cudaEventCreateWithFlags(&g_eD2,  cudaEventDisableTiming);
    }
} g_stream_init;

// ---------------------------------------------------------------------------
// helpers
// ---------------------------------------------------------------------------
__device__ __forceinline__ uint32_t smem_u32(const void* p) {
    uint32_t a;
    asm("{ .reg .u64 t; cvta.to.shared.u64 t, %1; cvt.u32.u64 %0, t; }" : "=r"(a) : "l"(p));
    return a;
}
__device__ __forceinline__ void cp16(uint32_t saddr, const void* g) {
    asm volatile("cp.async.cg.shared.global [%0], [%1], 16;" :: "r"(saddr), "l"(g));
}
#define CP_COMMIT() asm volatile("cp.async.commit_group;" ::: "memory")
#define CP_WAIT1()  asm volatile("cp.async.wait_group 1;" ::: "memory")

__device__ __forceinline__ void ldsm4(uint32_t r[4], uint32_t addr) {
    asm volatile("ldmatrix.sync.aligned.m8n8.x4.shared.b16 {%0,%1,%2,%3}, [%4];"
        : "=r"(r[0]), "=r"(r[1]), "=r"(r[2]), "=r"(r[3]) : "r"(addr));
}
__device__ __forceinline__ void mma_f16(float c[4], const uint32_t a[4], const uint32_t b[2]) {
    asm volatile("mma.sync.aligned.m16n8k16.row.col.f32.f16.f16.f32 "
        "{%0,%1,%2,%3}, {%4,%5,%6,%7}, {%8,%9}, {%0,%1,%2,%3};"
        : "+f"(c[0]), "+f"(c[1]), "+f"(c[2]), "+f"(c[3])
        : "r"(a[0]), "r"(a[1]), "r"(a[2]), "r"(a[3]), "r"(b[0]), "r"(b[1]));
}
__device__ __forceinline__ uint32_t packh2(float a, float b) {
    __half2 t = __floats2half2_rn(a, b);
    return *reinterpret_cast<uint32_t*>(&t);
}
// GELU, exact-erf via A&S 7.1.25 (3-term, |erf err| <= 2.5e-5)
__device__ __forceinline__ float gelu_f(float x) {
    const float z = fabsf(x) * 0.70710678118654752f;
    const float t = 1.0f / fmaf(0.47047f, z, 1.0f);
    const float q = t * fmaf(t, fmaf(t, 0.7478556f, -0.0958798f), 0.3480242f);
    const float e = __expf(-z * z);
    const float s = copysignf(fmaf(-q, e, 1.0f), x);
    const float hx = 0.5f * x;
    return fmaf(hx, s, hx);
}
// gumbel noise g = -log(-log(u)), accurate where it matters (u -> 1)
__device__ __forceinline__ float gumbel_f(float u) {
    const float r = 1.0f - u;
    float w;
    if (r < 0.25f) {
        w = r * fmaf(r, fmaf(r, fmaf(r, fmaf(r, fmaf(r, fmaf(r,
                0.14285714f, 0.16666667f), 0.2f), 0.25f), 0.33333333f), 0.5f), 1.0f);
    } else {
        w = -__logf(u);
    }
    return -__logf(w);
}

// ---------------------------------------------------------------------------
// fp16 GEMM via mma.sync (champion config): D = A @ B^T, 128x128 CTA tile,
// 8 warps (4m x 2n), K-chunk 64, cp.async 3-stage pipeline, 2 CTA/SM.
// Pipeline order: WAIT -> sync -> issue (do NOT reorder).
// EPI: 0 = fp32(+bias)
//      2 = scores: *scale + gumbel(U) -> fp32
//      3 = gelu(x+bias) -> fp16
//      5 = fused QKV: seg0/1/2 -> outh/outh2/outh3 (+bias/bias2/bias3), width 768
// ---------------------------------------------------------------------------
#define TSTRIDE 144
#define TILEB   (128*TSTRIDE)       // 18432
#define BUFB    (2*TILEB)
#define GSMEM   (3*BUFB)            // 110592

template<int EPI>
__global__ void __launch_bounds__(256, 2) gemm_mma(
    const __half* __restrict__ A, const __half* __restrict__ B,
    const float* __restrict__ bias, const float* __restrict__ bias2,
    const float* __restrict__ bias3, const float* __restrict__ U,
    float* __restrict__ outf, __half* __restrict__ outh,
    __half* __restrict__ outh2, __half* __restrict__ outh3,
    int N, int K, size_t sA, size_t sB, size_t sC)
{
    extern __shared__ char smem[];
    const uint32_t sb = smem_u32(smem);

    const int tid = threadIdx.x, wid = tid >> 5, lane = tid & 31;
    const int m0 = blockIdx.y * 128, n0 = blockIdx.x * 128;

    A += (size_t)blockIdx.z * sA;
    B += (size_t)blockIdx.z * sB;

    const int lrow = tid >> 3;
    const int lu   = tid & 7;
    const int nch = K >> 6;

    const int wm = wid & 3, wn = wid >> 2;
    const int arow = wm * 32 + (lane & 7) + ((lane >> 3) & 1) * 8;
    const int acol = ((lane >> 4) * 8) * 2;
    const int brow = wn * 64 + ((lane >> 4) << 3) + (lane & 7);
    const int bcol = (((lane >> 3) & 1) * 8) * 2;

    float acc[2][8][4];
    #pragma unroll
    for (int i = 0; i < 2; i++)
        #pragma unroll
        for (int j = 0; j < 8; j++)
            #pragma unroll
            for (int t = 0; t < 4; t++) acc[i][j][t] = 0.0f;

    auto issue = [&](int c, int buf) {
        const uint32_t dst = sb + buf * BUFB;
        const size_t kc = (size_t)c * 64;
        #pragma unroll
        for (int j = 0; j < 4; ++j) {
            const int row = lrow + j * 32;
            const size_t ga = (size_t)(m0 + row) * K + kc + lu * 8;
            const size_t gb = (size_t)(n0 + row) * K + kc + lu * 8;
            const uint32_t so = row * TSTRIDE + lu * 16;
            cp16(dst +         so, A + ga);
            cp16(dst + TILEB + so, B + gb);
        }
    };

    issue(0, 0); CP_COMMIT();
    issue(1, 1); CP_COMMIT();

    for (int c = 0; c < nch; ++c) {
        CP_WAIT1();                       // this thread's chunk-c copies done
        __syncthreads();                  // all threads' copies published
        if (c + 2 < nch) issue(c + 2, (c + 2) % 3);
        CP_COMMIT();

        const uint32_t ab = sb + (c % 3) * BUFB;
        const uint32_t bb = ab + TILEB;

        #pragma unroll
        for (int ks = 0; ks < 4; ++ks) {
            const int kb = ks * 32;
            uint32_t af[2][4];
            #pragma unroll
            for (int mf = 0; mf < 2; ++mf)
                ldsm4(af[mf], ab + (arow + mf*16) * TSTRIDE + kb + acol);
            uint32_t bf[8][2];
            #pragma unroll
            for (int g = 0; g < 4; ++g) {
                uint32_t r[4];
                ldsm4(r, bb + (brow + g*16) * TSTRIDE + kb + bcol);
                bf[g*2][0] = r[0];   bf[g*2][1] = r[1];
                bf[g*2+1][0] = r[2]; bf[g*2+1][1] = r[3];
            }
            #pragma unroll
            for (int mf = 0; mf < 2; ++mf)
                #pragma unroll
                for (int nf = 0; nf < 8; ++nf)
                    mma_f16(acc[mf][nf], af[mf], bf[nf]);
        }
    }

    // ---- epilogue
    const int colw = n0 + wn * 64 + (lane & 3) * 2;
    const int roww = m0 + wm * 32 + (lane >> 2);

    const int seg = (EPI == 5) ? (blockIdx.x / 6) : 0;
    const float* bsel = bias;
    __half* osel = outh;
    if (EPI == 5) {
        bsel = (seg == 0) ? bias : (seg == 1 ? bias2 : bias3);
        osel = (seg == 0) ? outh : (seg == 1 ? outh2 : outh3);
    }
    const int csub = (EPI == 5) ? seg * 768 : 0;
    const int NW = (EPI == 5) ? 768 : N;

    #pragma unroll
    for (int mf = 0; mf < 2; ++mf) {
        #pragma unroll
        for (int half = 0; half < 2; ++half) {
            const int row = roww + mf * 16 + half * 8;
            const size_t rb = (size_t)blockIdx.z * sC + (size_t)row * NW;
            #pragma unroll
            for (int nf = 0; nf < 8; ++nf) {
                const int col = colw + nf * 8 - csub;
                float v0 = acc[mf][nf][half*2 + 0];
                float v1 = acc[mf][nf][half*2 + 1];

                if (EPI == 2) {
                    const float scale = 0.03608439182435161f;
                    const float2 u = *(const float2*)&U[rb + col];
                    v0 = fmaf(v0, scale, gumbel_f(u.x));
                    v1 = fmaf(v1, scale, gumbel_f(u.y));
                    *(float2*)&outf[rb + col] = make_float2(v0, v1);
                } else if (EPI == 0) {
                    if (bias) { v0 += bias[col]; v1 += bias[col + 1]; }
                    *(float2*)&outf[rb + col] = make_float2(v0, v1);
                } else if (EPI == 3) {
                    v0 = gelu_f(v0 + bias[col]);
                    v1 = gelu_f(v1 + bias[col + 1]);
                    *(uint32_t*)&outh[rb + col] = packh2(v0, v1);
                } else {  // EPI == 5
                    v0 += bsel[col]; v1 += bsel[col + 1];
                    *(uint32_t*)&osel[rb + col] = packh2(v0, v1);
                }
            }
        }
    }
}

// ---------------------------------------------------------------------------
// elementwise kernels
// ---------------------------------------------------------------------------
__global__ void __launch_bounds__(256) convert_h_k(
    const float4* __restrict__ x, uint2* __restrict__ hi, int n4)
{
    for (int i = blockIdx.x * 256 + threadIdx.x; i < n4; i += gridDim.x * 256) {
        const float4 v = x[i];
        uint2 uh;
        uh.x = packh2(v.x, v.y);
        uh.y = packh2(v.z, v.w);
        hi[i] = uh;
    }
}

// batched QKV weight transpose: z selects wq/wk/wv -> wqkvh + z*DD*DD
__global__ void __launch_bounds__(256) transpose_qkv_k(
    const float* __restrict__ wq, const float* __restrict__ wk,
    const float* __restrict__ wv, __half* __restrict__ oh)
{
    __shared__ float t[32][33];
    const float* in = (blockIdx.z == 0) ? wq : (blockIdx.z == 1 ? wk : wv);
    __half* o = oh + (size_t)blockIdx.z * DD * DD;
    const int bx = blockIdx.x * 32, by = blockIdx.y * 32;
    const int tx = threadIdx.x, ty = threadIdx.y;

    #pragma unroll
    for (int i = ty; i < 32; i += 8)
        t[i][tx] = in[(size_t)(by + i) * DD + bx + tx];
    __syncthreads();
    #pragma unroll
    for (int i = ty; i < 32; i += 8)
        o[(size_t)(bx + i) * DD + by + tx] = __float2half_rn(t[tx][i]);
}

// out[c, r] = fp16(in[r, c])  (fp32 in).  grid(C/32, R/32, batch), block(32,8)
__global__ void __launch_bounds__(256) transpose_h_k(
    const float* __restrict__ in, __half* __restrict__ oh, int R, int C)
{
    __shared__ float t[32][33];
    const size_t boff = (size_t)blockIdx.z * R * C;
    const int bx = blockIdx.x * 32, by = blockIdx.y * 32;
    const int tx = threadIdx.x, ty = threadIdx.y;

    #pragma unroll
    for (int i = ty; i < 32; i += 8)
        t[i][tx] = in[boff + (size_t)(by + i) * C + bx + tx];
    __syncthreads();
    #pragma unroll
    for (int i = ty; i < 32; i += 8) {
        const size_t o = boff + (size_t)(bx + i) * R + by + tx;
        oh[o] = __float2half_rn(t[tx][i]);
    }
}

// out[c, r] = in[r, c]  (fp16 in/out).  grid(C/32, R/32, batch), block(32,8)
__global__ void __launch_bounds__(256) transpose_hh_k(
    const __half* __restrict__ in, __half* __restrict__ oh, int R, int C)
{
    __shared__ int t[32][33];
    const size_t boff = (size_t)blockIdx.z * R * C;
    const int bx = blockIdx.x * 32, by = blockIdx.y * 32;
    const int tx = threadIdx.x, ty = threadIdx.y;

    #pragma unroll
    for (int i = ty; i < 32; i += 8)
        t[i][tx] = (int)*(const unsigned short*)&in[boff + (size_t)(by + i) * C + bx + tx];
    __syncthreads();
    #pragma unroll
    for (int i = ty; i < 32; i += 8) {
        const size_t o = boff + (size_t)(bx + i) * R + by + tx;
        *(unsigned short*)&oh[o] = (unsigned short)t[tx][i];
    }
}

// softmax over rows of 1024, fp32 in -> fp16 out
__global__ void __launch_bounds__(256) softmax_h_k(
    const float* __restrict__ sc, __half* __restrict__ oh)
{
    __shared__ float red[8];
    const size_t rb = (size_t)blockIdx.x * SS;
    const int tid = threadIdx.x;
    float4 x = ((const float4*)(sc + rb))[tid];

    float m = fmaxf(fmaxf(x.x, x.y), fmaxf(x.z, x.w));
    #pragma unroll
    for (int o = 16; o; o >>= 1) m = fmaxf(m, __shfl_xor_sync(0xffffffffu, m, o));
    if ((tid & 31) == 0) red[tid >> 5] = m;
    __syncthreads();
    float bm = red[0];
    #pragma unroll
    for (int i = 1; i < 8; i++) bm = fmaxf(bm, red[i]);

    x.x = __expf(x.x - bm); x.y = __expf(x.y - bm);
    x.z = __expf(x.z - bm); x.w = __expf(x.w - bm);
    float s = x.x + x.y + x.z + x.w;
    #pragma unroll
    for (int o = 16; o; o >>= 1) s += __shfl_xor_sync(0xffffffffu, s, o);
    __syncthreads();
    if ((tid & 31) == 0) red[tid >> 5] = s;
    __syncthreads();
    float tot = 0.0f;
    #pragma unroll
    for (int i = 0; i < 8; i++) tot += red[i];

    const float inv = 1.0f / tot;
    uint2 uh;
    uh.x = packh2(x.x * inv, x.y * inv);
    uh.y = packh2(x.z * inv, x.w * inv);
    ((uint2*)(oh + rb))[tid] = uh;
}

// out = LN(a + r)*w + b, vectorized: 192 threads, one row, float4 lanes.
template<int TOH>
__global__ void __launch_bounds__(192) add_ln_k(
    const float* __restrict__ a, const float* __restrict__ r,
    const float* __restrict__ w, const float* __restrict__ bb,
    float* __restrict__ out, __half* __restrict__ oh)
{
    __shared__ float rs[6], rq[6];
    const size_t base = (size_t)blockIdx.x * DD;
    const int tid = threadIdx.x;

    const float4 av = ((const float4*)(a + base))[tid];
    const float4 rv = ((const float4*)(r + base))[tid];
    float x0 = av.x + rv.x, x1 = av.y + rv.y, x2 = av.z + rv.z, x3 = av.w + rv.w;

    float s = x0 + x1 + x2 + x3;
    float q = x0*x0 + x1*x1 + x2*x2 + x3*x3;
    #pragma unroll
    for (int o = 16; o; o >>= 1) {
        s += __shfl_xor_sync(0xffffffffu, s, o);
        q += __shfl_xor_sync(0xffffffffu, q, o);
    }
    if ((tid & 31) == 0) { rs[tid >> 5] = s; rq[tid >> 5] = q; }
    __syncthreads();
    float S_ = 0.0f, Q_ = 0.0f;
    #pragma unroll
    for (int i = 0; i < 6; i++) { S_ += rs[i]; Q_ += rq[i]; }

    const float invD = 1.0f / 768.0f;
    const float mean = S_ * invD;
    const float var  = Q_ * invD - mean * mean;
    const float inv  = rsqrtf(var + 1e-5f);

    const float4 wv = ((const float4*)w)[tid];
    const float4 bv = ((const float4*)bb)[tid];
    float4 o;
    o.x = (x0 - mean) * inv * wv.x + bv.x;
    o.y = (x1 - mean) * inv * wv.y + bv.y;
    o.z = (x2 - mean) * inv * wv.z + bv.z;
    o.w = (x3 - mean) * inv * wv.w + bv.w;
    ((float4*)(out + base))[tid] = o;
    if (TOH) {
        uint2 uh;
        uh.x = packh2(o.x, o.y);
        uh.y = packh2(o.z, o.w);
        ((uint2*)(oh + base))[tid] = uh;
    }
}

// ---------------------------------------------------------------------------
extern "C" void kernel_launch(void* const* d_in, const int* in_sizes, int n_in,
                              void* d_out, int out_size)
{
    const float* src  = (const float*)d_in[0];
    const float* gu   = (const float*)d_in[1];
    const float* wq   = (const float*)d_in[2];
    const float* bq   = (const float*)d_in[3];
    const float* wk   = (const float*)d_in[4];
    const float* bk   = (const float*)d_in[5];
    const float* wv   = (const float*)d_in[6];
    const float* bv   = (const float*)d_in[7];
    const float* w1   = (const float*)d_in[8];
    const float* b1   = (const float*)d_in[9];
    const float* w2   = (const float*)d_in[10];
    const float* b2   = (const float*)d_in[11];
    const float* ln1w = (const float*)d_in[12];
    const float* ln1b = (const float*)d_in[13];
    const float* ln2w = (const float*)d_in[14];
    const float* ln2b = (const float*)d_in[15];
    float* out = (float*)d_out;

    cudaFuncSetAttribute(gemm_mma<0>, cudaFuncAttributeMaxDynamicSharedMemorySize, GSMEM);
    cudaFuncSetAttribute(gemm_mma<2>, cudaFuncAttributeMaxDynamicSharedMemorySize, GSMEM);
    cudaFuncSetAttribute(gemm_mma<3>, cudaFuncAttributeMaxDynamicSharedMemorySize, GSMEM);
    cudaFuncSetAttribute(gemm_mma<5>, cudaFuncAttributeMaxDynamicSharedMemorySize, GSMEM);

    __half *srch, *wqkvh, *w1h, *w2h;
    __half *qh, *kh, *vh, *vth, *ah, *xh, *hh;
    float *v, *scores, *x;
    cudaGetSymbolAddress((void**)&srch, g_srch);
    cudaGetSymbolAddress((void**)&wqkvh, g_wqkvh);
    cudaGetSymbolAddress((void**)&w1h, g_w1h);
    cudaGetSymbolAddress((void**)&w2h, g_w2h);
    cudaGetSymbolAddress((void**)&qh, g_qh);
    cudaGetSymbolAddress((void**)&kh, g_kh);
    cudaGetSymbolAddress((void**)&vh, g_vh);
    cudaGetSymbolAddress((void**)&v, g_v);
    cudaGetSymbolAddress((void**)&vth, g_vth);
    cudaGetSymbolAddress((void**)&scores, g_scores);
    cudaGetSymbolAddress((void**)&ah, g_ah);
    cudaGetSymbolAddress((void**)&x, g_x);
    cudaGetSymbolAddress((void**)&xh, g_xh);
    cudaGetSymbolAddress((void**)&hh, g_hh);

    const size_t sSD = (size_t)SS * DD;
    const size_t sSS = (size_t)SS * SS;
    const size_t hSD = (size_t)MHALF * DD;
    const size_t hFF = (size_t)MHALF * DFFN;
    const int n4h = MTOT*DD/8;                 // float4 groups per half

    // ---- fork root ---------------------------------------------------------
    cudaEventRecord(g_eRoot, 0);
    cudaStreamWaitEvent(g_s1, g_eRoot, 0);
    cudaStreamWaitEvent(g_s2, g_eRoot, 0);
    cudaStreamWaitEvent(g_s3, g_eRoot, 0);
    cudaStreamWaitEvent(g_s4, g_eRoot, 0);
    cudaStreamWaitEvent(g_s5, g_eRoot, 0);

    // launch 0,1 (main): src -> fp16, in halves
    convert_h_k<<<6144, 256>>>((const float4*)src, (uint2*)srch, n4h);
    cudaEventRecord(g_eC1, 0);
    convert_h_k<<<6144, 256>>>((const float4*)(src + hSD), (uint2*)(srch + hSD), n4h);

    // launch 2 (s1): batched QKV weight transpose
    transpose_qkv_k<<<dim3(24, 24, 3), dim3(32, 8), 0, g_s1>>>(wq, wk, wv, wqkvh);
    cudaEventRecord(g_eW, g_s1);

    // launch 3 (main, ncu-profiled): fused QKV projection, half 1
    // (main stream: conv-h1 already precedes; only need weight event. Note
    //  conv-h2 also precedes on main, but it's tiny and fills idle SMs.)
    cudaStreamWaitEvent(0, g_eW, 0);
    gemm_mma<5><<<dim3(18, 64, 1), 256, GSMEM>>>(srch, wqkvh, bq, bk, bv, nullptr,
        nullptr, qh, kh, vh, 3*DD, DD, 0, 0, 0);
    cudaEventRecord(g_eQ1, 0);
    // QKV half 2
    gemm_mma<5><<<dim3(18, 64, 1), 256, GSMEM>>>(srch + hSD, wqkvh, bq, bk, bv, nullptr,
        nullptr, qh + hSD, kh + hSD, vh + hSD, 3*DD, DD, 0, 0, 0);
    cudaEventRecord(g_eQ2, 0);

    // s2: v^T transposes per half
    cudaStreamWaitEvent(g_s2, g_eQ1, 0);
    transpose_hh_k<<<dim3(24, 32, BH), dim3(32, 8), 0, g_s2>>>(vh, vth, SS, DD);
    cudaEventRecord(g_eV1, g_s2);
    cudaStreamWaitEvent(g_s2, g_eQ2, 0);
    transpose_hh_k<<<dim3(24, 32, BH), dim3(32, 8), 0, g_s2>>>(vh + hSD, vth + hSD, SS, DD);
    cudaEventRecord(g_eV2, g_s2);

    // s3: FFN weight transposes
    transpose_h_k<<<dim3(96, 24, 1), dim3(32, 8), 0, g_s3>>>(w1, w1h, DD, DFFN);
    transpose_h_k<<<dim3(24, 96, 1), dim3(32, 8), 0, g_s3>>>(w2, w2h, DFFN, DD);
    cudaEventRecord(g_eW12, g_s3);

    // ---- half-pipeline 1 on s4 (batches 0:8 / rows 0:8192) -----------------
    cudaStreamWaitEvent(g_s4, g_eQ1, 0);
    gemm_mma<2><<<dim3(8, 8, BH), 256, GSMEM, g_s4>>>(qh, kh, nullptr, nullptr, nullptr, gu,
        scores, nullptr, nullptr, nullptr, SS, DD, sSD, sSD, sSS);
    softmax_h_k<<<BH*SS, 256, 0, g_s4>>>(scores, ah);
    cudaStreamWaitEvent(g_s4, g_eV1, 0);
    gemm_mma<0><<<dim3(6, 8, BH), 256, GSMEM, g_s4>>>(ah, vth, nullptr, nullptr, nullptr, nullptr,
        v, nullptr, nullptr, nullptr, DD, SS, sSS, sSD, sSD);
    add_ln_k<1><<<MHALF, 192, 0, g_s4>>>(src, v, ln1w, ln1b, x, xh);
    cudaStreamWaitEvent(g_s4, g_eW12, 0);
    gemm_mma<3><<<dim3(24, 64, 1), 256, GSMEM, g_s4>>>(xh, w1h, b1, nullptr, nullptr, nullptr,
        nullptr, hh, nullptr, nullptr, DFFN, DD, 0, 0, 0);
    gemm_mma<0><<<dim3(6, 64, 1), 256, GSMEM, g_s4>>>(hh, w2h, b2, nullptr, nullptr, nullptr,
        scores, nullptr, nullptr, nullptr, DD, DFFN, 0, 0, 0);
    add_ln_k<0><<<MHALF, 192, 0, g_s4>>>(x, scores, ln2w, ln2b, out, nullptr);
    cudaEventRecord(g_eD1, g_s4);

    // ---- half-pipeline 2 on s5 (batches 8:16 / rows 8192:16384) ------------
    float* ff2 = scores + BH*sSS;   // own half's scores region (disjoint from h1 writes)
    cudaStreamWaitEvent(g_s5, g_eQ2, 0);
    gemm_mma<2><<<dim3(8, 8, BH), 256, GSMEM, g_s5>>>(qh + BH*sSD, kh + BH*sSD,
        nullptr, nullptr, nullptr, gu + BH*sSS,
        scores + BH*sSS, nullptr, nullptr, nullptr, SS, DD, sSD, sSD, sSS);
    softmax_h_k<<<BH*SS, 256, 0, g_s5>>>(scores + BH*sSS, ah + BH*sSS);
    cudaStreamWaitEvent(g_s5, g_eV2, 0);
    gemm_mma<0><<<dim3(6, 8, BH), 256, GSMEM, g_s5>>>(ah + BH*sSS, vth + BH*sSD,
        nullptr, nullptr, nullptr, nullptr,
        v + BH*sSD, nullptr, nullptr, nullptr, DD, SS, sSS, sSD, sSD);
    add_ln_k<1><<<MHALF, 192, 0, g_s5>>>(src + hSD, v + hSD, ln1w, ln1b, x + hSD, xh + hSD);
    cudaStreamWaitEvent(g_s5, g_eW12, 0);
    gemm_mma<3><<<dim3(24, 64, 1), 256, GSMEM, g_s5>>>(xh + hSD, w1h, b1, nullptr, nullptr, nullptr,
        nullptr, hh + hFF, nullptr, nullptr, DFFN, DD, 0, 0, 0);
    gemm_mma<0><<<dim3(6, 64, 1), 256, GSMEM, g_s5>>>(hh + hFF, w2h, b2, nullptr, nullptr, nullptr,
        ff2, nullptr, nullptr, nullptr, DD, DFFN, 0, 0, 0);
    add_ln_k<0><<<MHALF, 192, 0, g_s5>>>(x + hSD, ff2, ln2w, ln2b, out + hSD, nullptr);
    cudaEventRecord(g_eD2, g_s5);

    // join
    cudaStreamWaitEvent(0, g_eD1, 0);
    cudaStreamWaitEvent(0, g_eD2, 0);
}

// round 16
// speedup vs baseline: 1.0070x; 1.0070x over previous
#include <cuda_runtime.h>
#include <cuda_fp16.h>
#include <math.h>
#include <cstdint>

#define BB 16
#define SS 1024
#define DD 768
#define DFFN 3072
#define MTOT (BB*SS)   // 16384
#define MHALF (MTOT/2) // 8192
#define BH (BB/2)      // 8

// ---------------------------------------------------------------------------
// Static scratch (no runtime device-memory allocation)
// ---------------------------------------------------------------------------
__device__ __align__(128) __half g_srch[MTOT*DD];
__device__ __align__(128) __half g_wqkvh[3*DD*DD];             // [wq^T ; wk^T ; wv^T]
__device__ __align__(128) __half g_w1h[DD*DFFN], g_w2h[DD*DFFN];
__device__ __align__(128) __half g_qh[MTOT*DD], g_kh[MTOT*DD];
__device__ __align__(128) float  g_v[MTOT*DD];                 // attn_out fp32
__device__ __align__(128) __half g_vth[MTOT*DD];               // v^T per batch [768,1024]
__device__ __align__(128) float  g_scores[(size_t)BB*SS*SS];   // scores fp32; halves reused as ff
__device__ __align__(128) __half g_ah[(size_t)BB*SS*SS];
__device__ __align__(128) float  g_x[MTOT*DD];
__device__ __align__(128) __half g_xh[MTOT*DD];
__device__ __align__(128) __half g_hh[(size_t)MTOT*DFFN];

// ---------------------------------------------------------------------------
// streams/events: created once at static-init (host objects, pre-checkpoint)
// ---------------------------------------------------------------------------
static cudaStream_t g_s1, g_s3, g_s4, g_s5;
static cudaEvent_t  g_eRoot, g_eW, g_eQ1, g_eQ2, g_eW12, g_eD1, g_eD2;
static struct StreamInit {
    StreamInit() {
        cudaStreamCreateWithFlags(&g_s1, cudaStreamNonBlocking);
        cudaStreamCreateWithFlags(&g_s3, cudaStreamNonBlocking);
        cudaStreamCreateWithFlags(&g_s4, cudaStreamNonBlocking);
        cudaStreamCreateWithFlags(&g_s5, cudaStreamNonBlocking);
        cudaEventCreateWithFlags(&g_eRoot, cudaEventDisableTiming);
        cudaEventCreateWithFlags(&g_eW,   cudaEventDisableTiming);
        cudaEventCreateWithFlags(&g_eQ1,  cudaEventDisableTiming);
        cudaEventCreateWithFlags(&g_eQ2,  cudaEventDisableTiming);
        cudaEventCreateWithFlags(&g_eW12, cudaEventDisableTiming);
        cudaEventCreateWithFlags(&g_eD1,  cudaEventDisableTiming);
        cudaEventCreateWithFlags(&g_eD2,  cudaEventDisableTiming);
    }
} g_stream_init;

// ---------------------------------------------------------------------------
// helpers
// ---------------------------------------------------------------------------
__device__ __forceinline__ uint32_t smem_u32(const void* p) {
    uint32_t a;
    asm("{ .reg .u64 t; cvta.to.shared.u64 t, %1; cvt.u32.u64 %0, t; }" : "=r"(a) : "l"(p));
    return a;
}
__device__ __forceinline__ void cp16(uint32_t saddr, const void* g) {
    asm volatile("cp.async.cg.shared.global [%0], [%1], 16;" :: "r"(saddr), "l"(g));
}
#define CP_COMMIT() asm volatile("cp.async.commit_group;" ::: "memory")
#define CP_WAIT1()  asm volatile("cp.async.wait_group 1;" ::: "memory")

__device__ __forceinline__ void ldsm4(uint32_t r[4], uint32_t addr) {
    asm volatile("ldmatrix.sync.aligned.m8n8.x4.shared.b16 {%0,%1,%2,%3}, [%4];"
        : "=r"(r[0]), "=r"(r[1]), "=r"(r[2]), "=r"(r[3]) : "r"(addr));
}
__device__ __forceinline__ void mma_f16(float c[4], const uint32_t a[4], const uint32_t b[2]) {
    asm volatile("mma.sync.aligned.m16n8k16.row.col.f32.f16.f16.f32 "
        "{%0,%1,%2,%3}, {%4,%5,%6,%7}, {%8,%9}, {%0,%1,%2,%3};"
        : "+f"(c[0]), "+f"(c[1]), "+f"(c[2]), "+f"(c[3])
        : "r"(a[0]), "r"(a[1]), "r"(a[2]), "r"(a[3]), "r"(b[0]), "r"(b[1]));
}
__device__ __forceinline__ uint32_t packh2(float a, float b) {
    __half2 t = __floats2half2_rn(a, b);
    return *reinterpret_cast<uint32_t*>(&t);
}
// GELU, exact-erf via A&S 7.1.25 (3-term, |erf err| <= 2.5e-5)
__device__ __forceinline__ float gelu_f(float x) {
    const float z = fabsf(x) * 0.70710678118654752f;
    const float t = 1.0f / fmaf(0.47047f, z, 1.0f);
    const float q = t * fmaf(t, fmaf(t, 0.7478556f, -0.0958798f), 0.3480242f);
    const float e = __expf(-z * z);
    const float s = copysignf(fmaf(-q, e, 1.0f), x);
    const float hx = 0.5f * x;
    return fmaf(hx, s, hx);
}
// gumbel noise g = -log(-log(u)), accurate where it matters (u -> 1)
__device__ __forceinline__ float gumbel_f(float u) {
    const float r = 1.0f - u;
    float w;
    if (r < 0.25f) {
        w = r * fmaf(r, fmaf(r, fmaf(r, fmaf(r, fmaf(r, fmaf(r,
                0.14285714f, 0.16666667f), 0.2f), 0.25f), 0.33333333f), 0.5f), 1.0f);
    } else {
        w = -__logf(u);
    }
    return -__logf(w);
}

// ---------------------------------------------------------------------------
// fp16 GEMM via mma.sync (champion config): D = A @ B^T, 128x128 CTA tile,
// 8 warps (4m x 2n), K-chunk 64, cp.async 3-stage pipeline, 2 CTA/SM.
// Pipeline order: WAIT -> sync -> issue (do NOT reorder).
// EPI: 0 = fp32(+bias)
//      2 = scores: *scale + gumbel(U) -> fp32
//      3 = gelu(x+bias) -> fp16
//      5 = fused QKV: seg0 -> outh(q), seg1 -> outh2(k), seg2 -> outh3 = v^T
//          (per-batch [768,1024] transposed store), width 768 each
// ---------------------------------------------------------------------------
#define TSTRIDE 144
#define TILEB   (128*TSTRIDE)       // 18432
#define BUFB    (2*TILEB)
#define GSMEM   (3*BUFB)            // 110592

template<int EPI>
__global__ void __launch_bounds__(256, 2) gemm_mma(
    const __half* __restrict__ A, const __half* __restrict__ B,
    const float* __restrict__ bias, const float* __restrict__ bias2,
    const float* __restrict__ bias3, const float* __restrict__ U,
    float* __restrict__ outf, __half* __restrict__ outh,
    __half* __restrict__ outh2, __half* __restrict__ outh3,
    int N, int K, size_t sA, size_t sB, size_t sC)
{
    extern __shared__ char smem[];
    const uint32_t sb = smem_u32(smem);

    const int tid = threadIdx.x, wid = tid >> 5, lane = tid & 31;
    const int m0 = blockIdx.y * 128, n0 = blockIdx.x * 128;

    A += (size_t)blockIdx.z * sA;
    B += (size_t)blockIdx.z * sB;

    const int lrow = tid >> 3;
    const int lu   = tid & 7;
    const int nch = K >> 6;

    const int wm = wid & 3, wn = wid >> 2;
    const int arow = wm * 32 + (lane & 7) + ((lane >> 3) & 1) * 8;
    const int acol = ((lane >> 4) * 8) * 2;
    const int brow = wn * 64 + ((lane >> 4) << 3) + (lane & 7);
    const int bcol = (((lane >> 3) & 1) * 8) * 2;

    float acc[2][8][4];
    #pragma unroll
    for (int i = 0; i < 2; i++)
        #pragma unroll
        for (int j = 0; j < 8; j++)
            #pragma unroll
            for (int t = 0; t < 4; t++) acc[i][j][t] = 0.0f;

    auto issue = [&](int c, int buf) {
        const uint32_t dst = sb + buf * BUFB;
        const size_t kc = (size_t)c * 64;
        #pragma unroll
        for (int j = 0; j < 4; ++j) {
            const int row = lrow + j * 32;
            const size_t ga = (size_t)(m0 + row) * K + kc + lu * 8;
            const size_t gb = (size_t)(n0 + row) * K + kc + lu * 8;
            const uint32_t so = row * TSTRIDE + lu * 16;
            cp16(dst +         so, A + ga);
            cp16(dst + TILEB + so, B + gb);
        }
    };

    issue(0, 0); CP_COMMIT();
    issue(1, 1); CP_COMMIT();

    for (int c = 0; c < nch; ++c) {
        CP_WAIT1();                       // this thread's chunk-c copies done
        __syncthreads();                  // all threads' copies published
        if (c + 2 < nch) issue(c + 2, (c + 2) % 3);
        CP_COMMIT();

        const uint32_t ab = sb + (c % 3) * BUFB;
        const uint32_t bb = ab + TILEB;

        #pragma unroll
        for (int ks = 0; ks < 4; ++ks) {
            const int kb = ks * 32;
            uint32_t af[2][4];
            #pragma unroll
            for (int mf = 0; mf < 2; ++mf)
                ldsm4(af[mf], ab + (arow + mf*16) * TSTRIDE + kb + acol);
            uint32_t bf[8][2];
            #pragma unroll
            for (int g = 0; g < 4; ++g) {
                uint32_t r[4];
                ldsm4(r, bb + (brow + g*16) * TSTRIDE + kb + bcol);
                bf[g*2][0] = r[0];   bf[g*2][1] = r[1];
                bf[g*2+1][0] = r[2]; bf[g*2+1][1] = r[3];
            }
            #pragma unroll
            for (int mf = 0; mf < 2; ++mf)
                #pragma unroll
                for (int nf = 0; nf < 8; ++nf)
                    mma_f16(acc[mf][nf], af[mf], bf[nf]);
        }
    }

    // ---- epilogue
    const int colw = n0 + wn * 64 + (lane & 3) * 2;
    const int roww = m0 + wm * 32 + (lane >> 2);

    const int seg = (EPI == 5) ? (blockIdx.x / 6) : 0;
    const float* bsel = bias;
    __half* osel = outh;
    if (EPI == 5) {
        bsel = (seg == 0) ? bias : (seg == 1 ? bias2 : bias3);
        osel = (seg == 0) ? outh : (seg == 1 ? outh2 : outh3);
    }
    const int csub = (EPI == 5) ? seg * 768 : 0;
    const int NW = (EPI == 5) ? 768 : N;

    #pragma unroll
    for (int mf = 0; mf < 2; ++mf) {
        #pragma unroll
        for (int half = 0; half < 2; ++half) {
            const int row = roww + mf * 16 + half * 8;
            const size_t rb = (size_t)blockIdx.z * sC + (size_t)row * NW;
            #pragma unroll
            for (int nf = 0; nf < 8; ++nf) {
                const int col = colw + nf * 8 - csub;
                float v0 = acc[mf][nf][half*2 + 0];
                float v1 = acc[mf][nf][half*2 + 1];

                if (EPI == 2) {
                    const float scale = 0.03608439182435161f;
                    const float2 u = *(const float2*)&U[rb + col];
                    v0 = fmaf(v0, scale, gumbel_f(u.x));
                    v1 = fmaf(v1, scale, gumbel_f(u.y));
                    *(float2*)&outf[rb + col] = make_float2(v0, v1);
                } else if (EPI == 0) {
                    if (bias) { v0 += bias[col]; v1 += bias[col + 1]; }
                    *(float2*)&outf[rb + col] = make_float2(v0, v1);
                } else if (EPI == 3) {
                    v0 = gelu_f(v0 + bias[col]);
                    v1 = gelu_f(v1 + bias[col + 1]);
                    *(uint32_t*)&outh[rb + col] = packh2(v0, v1);
                } else {  // EPI == 5
                    v0 += bsel[col]; v1 += bsel[col + 1];
                    if (seg < 2) {
                        *(uint32_t*)&osel[rb + (size_t)row * 0 + col
                                          + (size_t)row * 768 - (size_t)row * 768]
                            = packh2(v0, v1);   // placeholder removed below
                        *(uint32_t*)&osel[(size_t)row * 768 + col] = packh2(v0, v1);
                    } else {
                        // V: write transposed, per-batch [768,1024]
                        const int b = row >> 10, s = row & 1023;
                        const size_t base = (size_t)b * (768*1024) + s;
                        osel[base + (size_t)col * 1024]       = __float2half_rn(v0);
                        osel[base + (size_t)(col + 1) * 1024] = __float2half_rn(v1);
                    }
                }
            }
        }
    }
}

// ---------------------------------------------------------------------------
// elementwise kernels
// ---------------------------------------------------------------------------
__global__ void __launch_bounds__(256) convert_h_k(
    const float4* __restrict__ x, uint2* __restrict__ hi, int n4)
{
    for (int i = blockIdx.x * 256 + threadIdx.x; i < n4; i += gridDim.x * 256) {
        const float4 v = x[i];
        uint2 uh;
        uh.x = packh2(v.x, v.y);
        uh.y = packh2(v.z, v.w);
        hi[i] = uh;
    }
}

// batched QKV weight transpose: z selects wq/wk/wv -> wqkvh + z*DD*DD
__global__ void __launch_bounds__(256) transpose_qkv_k(
    const float* __restrict__ wq, const float* __restrict__ wk,
    const float* __restrict__ wv, __half* __restrict__ oh)
{
    __shared__ float t[32][33];
    const float* in = (blockIdx.z == 0) ? wq : (blockIdx.z == 1 ? wk : wv);
    __half* o = oh + (size_t)blockIdx.z * DD * DD;
    const int bx = blockIdx.x * 32, by = blockIdx.y * 32;
    const int tx = threadIdx.x, ty = threadIdx.y;

    #pragma unroll
    for (int i = ty; i < 32; i += 8)
        t[i][tx] = in[(size_t)(by + i) * DD + bx + tx];
    __syncthreads();
    #pragma unroll
    for (int i = ty; i < 32; i += 8)
        o[(size_t)(bx + i) * DD + by + tx] = __float2half_rn(t[tx][i]);
}

// out[c, r] = fp16(in[r, c])  (fp32 in).  grid(C/32, R/32, batch), block(32,8)
__global__ void __launch_bounds__(256) transpose_h_k(
    const float* __restrict__ in, __half* __restrict__ oh, int R, int C)
{
    __shared__ float t[32][33];
    const size_t boff = (size_t)blockIdx.z * R * C;
    const int bx = blockIdx.x * 32, by = blockIdx.y * 32;
    const int tx = threadIdx.x, ty = threadIdx.y;

    #pragma unroll
    for (int i = ty; i < 32; i += 8)
        t[i][tx] = in[boff + (size_t)(by + i) * C + bx + tx];
    __syncthreads();
    #pragma unroll
    for (int i = ty; i < 32; i += 8) {
        const size_t o = boff + (size_t)(bx + i) * R + by + tx;
        oh[o] = __float2half_rn(t[tx][i]);
    }
}

// softmax over rows of 1024, fp32 in -> fp16 out
__global__ void __launch_bounds__(256) softmax_h_k(
    const float* __restrict__ sc, __half* __restrict__ oh)
{
    __shared__ float red[8];
    const size_t rb = (size_t)blockIdx.x * SS;
    const int tid = threadIdx.x;
    float4 x = ((const float4*)(sc + rb))[tid];

    float m = fmaxf(fmaxf(x.x, x.y), fmaxf(x.z, x.w));
    #pragma unroll
    for (int o = 16; o; o >>= 1) m = fmaxf(m, __shfl_xor_sync(0xffffffffu, m, o));
    if ((tid & 31) == 0) red[tid >> 5] = m;
    __syncthreads();
    float bm = red[0];
    #pragma unroll
    for (int i = 1; i < 8; i++) bm = fmaxf(bm, red[i]);

    x.x = __expf(x.x - bm); x.y = __expf(x.y - bm);
    x.z = __expf(x.z - bm); x.w = __expf(x.w - bm);
    float s = x.x + x.y + x.z + x.w;
    #pragma unroll
    for (int o = 16; o; o >>= 1) s += __shfl_xor_sync(0xffffffffu, s, o);
    __syncthreads();
    if ((tid & 31) == 0) red[tid >> 5] = s;
    __syncthreads();
    float tot = 0.0f;
    #pragma unroll
    for (int i = 0; i < 8; i++) tot += red[i];

    const float inv = 1.0f / tot;
    uint2 uh;
    uh.x = packh2(x.x * inv, x.y * inv);
    uh.y = packh2(x.z * inv, x.w * inv);
    ((uint2*)(oh + rb))[tid] = uh;
}

// out = LN(a + r)*w + b, vectorized: 192 threads, one row, float4 lanes.
template<int TOH>
__global__ void __launch_bounds__(192) add_ln_k(
    const float* __restrict__ a, const float* __restrict__ r,
    const float* __restrict__ w, const float* __restrict__ bb,
    float* __restrict__ out, __half* __restrict__ oh)
{
    __shared__ float rs[6], rq[6];
    const size_t base = (size_t)blockIdx.x * DD;
    const int tid = threadIdx.x;

    const float4 av = ((const float4*)(a + base))[tid];
    const float4 rv = ((const float4*)(r + base))[tid];
    float x0 = av.x + rv.x, x1 = av.y + rv.y, x2 = av.z + rv.z, x3 = av.w + rv.w;

    float s = x0 + x1 + x2 + x3;
    float q = x0*x0 + x1*x1 + x2*x2 + x3*x3;
    #pragma unroll
    for (int o = 16; o; o >>= 1) {
        s += __shfl_xor_sync(0xffffffffu, s, o);
        q += __shfl_xor_sync(0xffffffffu, q, o);
    }
    if ((tid & 31) == 0) { rs[tid >> 5] = s; rq[tid >> 5] = q; }
    __syncthreads();
    float S_ = 0.0f, Q_ = 0.0f;
    #pragma unroll
    for (int i = 0; i < 6; i++) { S_ += rs[i]; Q_ += rq[i]; }

    const float invD = 1.0f / 768.0f;
    const float mean = S_ * invD;
    const float var  = Q_ * invD - mean * mean;
    const float inv  = rsqrtf(var + 1e-5f);

    const float4 wv = ((const float4*)w)[tid];
    const float4 bv = ((const float4*)bb)[tid];
    float4 o;
    o.x = (x0 - mean) * inv * wv.x + bv.x;
    o.y = (x1 - mean) * inv * wv.y + bv.y;
    o.z = (x2 - mean) * inv * wv.z + bv.z;
    o.w = (x3 - mean) * inv * wv.w + bv.w;
    ((float4*)(out + base))[tid] = o;
    if (TOH) {
        uint2 uh;
        uh.x = packh2(o.x, o.y);
        uh.y = packh2(o.z, o.w);
        ((uint2*)(oh + base))[tid] = uh;
    }
}

// ---------------------------------------------------------------------------
extern "C" void kernel_launch(void* const* d_in, const int* in_sizes, int n_in,
                              void* d_out, int out_size)
{
    const float* src  = (const float*)d_in[0];
    const float* gu   = (const float*)d_in[1];
    const float* wq   = (const float*)d_in[2];
    const float* bq   = (const float*)d_in[3];
    const float* wk   = (const float*)d_in[4];
    const float* bk   = (const float*)d_in[5];
    const float* wv   = (const float*)d_in[6];
    const float* bv   = (const float*)d_in[7];
    const float* w1   = (const float*)d_in[8];
    const float* b1   = (const float*)d_in[9];
    const float* w2   = (const float*)d_in[10];
    const float* b2   = (const float*)d_in[11];
    const float* ln1w = (const float*)d_in[12];
    const float* ln1b = (const float*)d_in[13];
    const float* ln2w = (const float*)d_in[14];
    const float* ln2b = (const float*)d_in[15];
    float* out = (float*)d_out;

    cudaFuncSetAttribute(gemm_mma<0>, cudaFuncAttributeMaxDynamicSharedMemorySize, GSMEM);
    cudaFuncSetAttribute(gemm_mma<2>, cudaFuncAttributeMaxDynamicSharedMemorySize, GSMEM);
    cudaFuncSetAttribute(gemm_mma<3>, cudaFuncAttributeMaxDynamicSharedMemorySize, GSMEM);
    cudaFuncSetAttribute(gemm_mma<5>, cudaFuncAttributeMaxDynamicSharedMemorySize, GSMEM);

    __half *srch, *wqkvh, *w1h, *w2h;
    __half *qh, *kh, *vth, *ah, *xh, *hh;
    float *v, *scores, *x;
    cudaGetSymbolAddress((void**)&srch, g_srch);
    cudaGetSymbolAddress((void**)&wqkvh, g_wqkvh);
    cudaGetSymbolAddress((void**)&w1h, g_w1h);
    cudaGetSymbolAddress((void**)&w2h, g_w2h);
    cudaGetSymbolAddress((void**)&qh, g_qh);
    cudaGetSymbolAddress((void**)&kh, g_kh);
    cudaGetSymbolAddress((void**)&vth, g_vth);
    cudaGetSymbolAddress((void**)&v, g_v);
    cudaGetSymbolAddress((void**)&scores, g_scores);
    cudaGetSymbolAddress((void**)&ah, g_ah);
    cudaGetSymbolAddress((void**)&x, g_x);
    cudaGetSymbolAddress((void**)&xh, g_xh);
    cudaGetSymbolAddress((void**)&hh, g_hh);

    const size_t sSD = (size_t)SS * DD;
    const size_t sSS = (size_t)SS * SS;
    const size_t hSD = (size_t)MHALF * DD;
    const size_t hFF = (size_t)MHALF * DFFN;
    const int n4h = MTOT*DD/8;

    // ---- fork root ---------------------------------------------------------
    cudaEventRecord(g_eRoot, 0);
    cudaStreamWaitEvent(g_s1, g_eRoot, 0);
    cudaStreamWaitEvent(g_s3, g_eRoot, 0);
    cudaStreamWaitEvent(g_s4, g_eRoot, 0);
    cudaStreamWaitEvent(g_s5, g_eRoot, 0);

    // launch 0,1 (main): src -> fp16, in halves
    convert_h_k<<<6144, 256>>>((const float4*)src, (uint2*)srch, n4h);
    convert_h_k<<<6144, 256>>>((const float4*)(src + hSD), (uint2*)(srch + hSD), n4h);

    // launch 2 (s1): batched QKV weight transpose
    transpose_qkv_k<<<dim3(24, 24, 3), dim3(32, 8), 0, g_s1>>>(wq, wk, wv, wqkvh);
    cudaEventRecord(g_eW, g_s1);

    // launch 3 (main, ncu-profiled): fused QKV projection, half 1
    cudaStreamWaitEvent(0, g_eW, 0);
    gemm_mma<5><<<dim3(18, 64, 1), 256, GSMEM>>>(srch, wqkvh, bq, bk, bv, nullptr,
        nullptr, qh, kh, vth, 3*DD, DD, 0, 0, 0);
    cudaEventRecord(g_eQ1, 0);
    // QKV half 2
    gemm_mma<5><<<dim3(18, 64, 1), 256, GSMEM>>>(srch + hSD, wqkvh, bq, bk, bv, nullptr,
        nullptr, qh + hSD, kh + hSD, vth + hSD, 3*DD, DD, 0, 0, 0);
    cudaEventRecord(g_eQ2, 0);

    // s3: FFN weight transposes
    transpose_h_k<<<dim3(96, 24, 1), dim3(32, 8), 0, g_s3>>>(w1, w1h, DD, DFFN);
    transpose_h_k<<<dim3(24, 96, 1), dim3(32, 8), 0, g_s3>>>(w2, w2h, DFFN, DD);
    cudaEventRecord(g_eW12, g_s3);

    // ---- half-pipeline 1 on s4 (batches 0:8 / rows 0:8192) -----------------
    cudaStreamWaitEvent(g_s4, g_eQ1, 0);
    gemm_mma<2><<<dim3(8, 8, BH), 256, GSMEM, g_s4>>>(qh, kh, nullptr, nullptr, nullptr, gu,
        scores, nullptr, nullptr, nullptr, SS, DD, sSD, sSD, sSS);
    softmax_h_k<<<BH*SS, 256, 0, g_s4>>>(scores, ah);
    gemm_mma<0><<<dim3(6, 8, BH), 256, GSMEM, g_s4>>>(ah, vth, nullptr, nullptr, nullptr, nullptr,
        v, nullptr, nullptr, nullptr, DD, SS, sSS, sSD, sSD);
    add_ln_k<1><<<MHALF, 192, 0, g_s4>>>(src, v, ln1w, ln1b, x, xh);
    cudaStreamWaitEvent(g_s4, g_eW12, 0);
    gemm_mma<3><<<dim3(24, 64, 1), 256, GSMEM, g_s4>>>(xh, w1h, b1, nullptr, nullptr, nullptr,
        nullptr, hh, nullptr, nullptr, DFFN, DD, 0, 0, 0);
    gemm_mma<0><<<dim3(6, 64, 1), 256, GSMEM, g_s4>>>(hh, w2h, b2, nullptr, nullptr, nullptr,
        scores, nullptr, nullptr, nullptr, DD, DFFN, 0, 0, 0);
    add_ln_k<0><<<MHALF, 192, 0, g_s4>>>(x, scores, ln2w, ln2b, out, nullptr);
    cudaEventRecord(g_eD1, g_s4);

    // ---- half-pipeline 2 on s5 (batches 8:16 / rows 8192:16384) ------------
    float* ff2 = scores + BH*sSS;   // own half's scores region (disjoint from h1 writes)
    cudaStreamWaitEvent(g_s5, g_eQ2, 0);
    gemm_mma<2><<<dim3(8, 8, BH), 256, GSMEM, g_s5>>>(qh + BH*sSD, kh + BH*sSD,
        nullptr, nullptr, nullptr, gu + BH*sSS,
        scores + BH*sSS, nullptr, nullptr, nullptr, SS, DD, sSD, sSD, sSS);
    softmax_h_k<<<BH*SS, 256, 0, g_s5>>>(scores + BH*sSS, ah + BH*sSS);
    gemm_mma<0><<<dim3(6, 8, BH), 256, GSMEM, g_s5>>>(ah + BH*sSS, vth + BH*sSD,
        nullptr, nullptr, nullptr, nullptr,
        v + BH*sSD, nullptr, nullptr, nullptr, DD, SS, sSS, sSD, sSD);
    add_ln_k<1><<<MHALF, 192, 0, g_s5>>>(src + hSD, v + hSD, ln1w, ln1b, x + hSD, xh + hSD);
    cudaStreamWaitEvent(g_s5, g_eW12, 0);
    gemm_mma<3><<<dim3(24, 64, 1), 256, GSMEM, g_s5>>>(xh + hSD, w1h, b1, nullptr, nullptr, nullptr,
        nullptr, hh + hFF, nullptr, nullptr, DFFN, DD, 0, 0, 0);
    gemm_mma<0><<<dim3(6, 64, 1), 256, GSMEM, g_s5>>>(hh + hFF, w2h, b2, nullptr, nullptr, nullptr,
        ff2, nullptr, nullptr, nullptr, DD, DFFN, 0, 0, 0);
    add_ln_k<0><<<MHALF, 192, 0, g_s5>>>(x + hSD, ff2, ln2w, ln2b, out + hSD, nullptr);
    cudaEventRecord(g_eD2, g_s5);

    // join
    cudaStreamWaitEvent(0, g_eD1, 0);
    cudaStreamWaitEvent(0, g_eD2, 0);
}

// round 17
// speedup vs baseline: 1.0228x; 1.0157x over previous
#include <cuda_runtime.h>
#include <cuda_fp16.h>
#include <math.h>
#include <cstdint>

#define BB 16
#define SS 1024
#define DD 768
#define DFFN 3072
#define MTOT (BB*SS)   // 16384
#define MHALF (MTOT/2) // 8192
#define BH (BB/2)      // 8

// ---------------------------------------------------------------------------
// Static scratch (no runtime device-memory allocation)
// ---------------------------------------------------------------------------
__device__ __align__(128) __half g_srch[MTOT*DD];
__device__ __align__(128) __half g_wqkvh[3*DD*DD];             // [wq^T ; wk^T ; wv^T]
__device__ __align__(128) __half g_w1h[DD*DFFN], g_w2h[DD*DFFN];
__device__ __align__(128) __half g_qh[MTOT*DD], g_kh[MTOT*DD];
__device__ __align__(128) float  g_v[MTOT*DD];                 // attn_out fp32
__device__ __align__(128) __half g_vth[MTOT*DD];               // v^T per batch [768,1024]
__device__ __align__(128) float  g_scores[(size_t)BB*SS*SS];   // scores fp32; halves reused as ff
__device__ __align__(128) __half g_ah[(size_t)BB*SS*SS];
__device__ __align__(128) float  g_x[MTOT*DD];
__device__ __align__(128) __half g_xh[MTOT*DD];
__device__ __align__(128) __half g_hh[(size_t)MTOT*DFFN];

// ---------------------------------------------------------------------------
// streams/events: created once at static-init (host objects, pre-checkpoint)
// ---------------------------------------------------------------------------
static cudaStream_t g_s1, g_s3, g_s4, g_s5;
static cudaEvent_t  g_eRoot, g_eW, g_eQ1, g_eQ2, g_eW12, g_eD1, g_eD2;
static struct StreamInit {
    StreamInit() {
        cudaStreamCreateWithFlags(&g_s1, cudaStreamNonBlocking);
        cudaStreamCreateWithFlags(&g_s3, cudaStreamNonBlocking);
        cudaStreamCreateWithFlags(&g_s4, cudaStreamNonBlocking);
        cudaStreamCreateWithFlags(&g_s5, cudaStreamNonBlocking);
        cudaEventCreateWithFlags(&g_eRoot, cudaEventDisableTiming);
        cudaEventCreateWithFlags(&g_eW,   cudaEventDisableTiming);
        cudaEventCreateWithFlags(&g_eQ1,  cudaEventDisableTiming);
        cudaEventCreateWithFlags(&g_eQ2,  cudaEventDisableTiming);
        cudaEventCreateWithFlags(&g_eW12, cudaEventDisableTiming);
        cudaEventCreateWithFlags(&g_eD1,  cudaEventDisableTiming);
        cudaEventCreateWithFlags(&g_eD2,  cudaEventDisableTiming);
    }
} g_stream_init;

// ---------------------------------------------------------------------------
// helpers
// ---------------------------------------------------------------------------
__device__ __forceinline__ uint32_t smem_u32(const void* p) {
    uint32_t a;
    asm("{ .reg .u64 t; cvta.to.shared.u64 t, %1; cvt.u32.u64 %0, t; }" : "=r"(a) : "l"(p));
    return a;
}
__device__ __forceinline__ void cp16(uint32_t saddr, const void* g) {
    asm volatile("cp.async.cg.shared.global [%0], [%1], 16;" :: "r"(saddr), "l"(g));
}
#define CP_COMMIT() asm volatile("cp.async.commit_group;" ::: "memory")
#define CP_WAIT1()  asm volatile("cp.async.wait_group 1;" ::: "memory")

__device__ __forceinline__ void ldsm4(uint32_t r[4], uint32_t addr) {
    asm volatile("ldmatrix.sync.aligned.m8n8.x4.shared.b16 {%0,%1,%2,%3}, [%4];"
        : "=r"(r[0]), "=r"(r[1]), "=r"(r[2]), "=r"(r[3]) : "r"(addr));
}
__device__ __forceinline__ void mma_f16(float c[4], const uint32_t a[4], const uint32_t b[2]) {
    asm volatile("mma.sync.aligned.m16n8k16.row.col.f32.f16.f16.f32 "
        "{%0,%1,%2,%3}, {%4,%5,%6,%7}, {%8,%9}, {%0,%1,%2,%3};"
        : "+f"(c[0]), "+f"(c[1]), "+f"(c[2]), "+f"(c[3])
        : "r"(a[0]), "r"(a[1]), "r"(a[2]), "r"(a[3]), "r"(b[0]), "r"(b[1]));
}
__device__ __forceinline__ uint32_t packh2(float a, float b) {
    __half2 t = __floats2half2_rn(a, b);
    return *reinterpret_cast<uint32_t*>(&t);
}
// GELU, exact-erf via A&S 7.1.25 (3-term, |erf err| <= 2.5e-5)
__device__ __forceinline__ float gelu_f(float x) {
    const float z = fabsf(x) * 0.70710678118654752f;
    const float t = 1.0f / fmaf(0.47047f, z, 1.0f);
    const float q = t * fmaf(t, fmaf(t, 0.7478556f, -0.0958798f), 0.3480242f);
    const float e = __expf(-z * z);
    const float s = copysignf(fmaf(-q, e, 1.0f), x);
    const float hx = 0.5f * x;
    return fmaf(hx, s, hx);
}
// gumbel noise g = -log(-log(u)), accurate where it matters (u -> 1)
__device__ __forceinline__ float gumbel_f(float u) {
    const float r = 1.0f - u;
    float w;
    if (r < 0.25f) {
        w = r * fmaf(r, fmaf(r, fmaf(r, fmaf(r, fmaf(r, fmaf(r,
                0.14285714f, 0.16666667f), 0.2f), 0.25f), 0.33333333f), 0.5f), 1.0f);
    } else {
        w = -__logf(u);
    }
    return -__logf(w);
}

// ---------------------------------------------------------------------------
// fp16 GEMM via mma.sync (champion config): D = A @ B^T, 128x128 CTA tile,
// 8 warps (4m x 2n), K-chunk 64, cp.async 3-stage pipeline, 2 CTA/SM.
// Pipeline order: WAIT -> sync -> issue (do NOT reorder).
// EPI: 0 = fp32(+bias)
//      2 = scores: *scale + gumbel(U) -> fp32
//      3 = gelu(x+bias) -> fp16
//      5 = fused QKV: seg0 -> outh(q), seg1 -> outh2(k), seg2 -> outh3 = v^T
//          (per-batch [768,1024] transposed store), width 768 each
// ---------------------------------------------------------------------------
#define TSTRIDE 144
#define TILEB   (128*TSTRIDE)       // 18432
#define BUFB    (2*TILEB)
#define GSMEM   (3*BUFB)            // 110592

template<int EPI>
__global__ void __launch_bounds__(256, 2) gemm_mma(
    const __half* __restrict__ A, const __half* __restrict__ B,
    const float* __restrict__ bias, const float* __restrict__ bias2,
    const float* __restrict__ bias3, const float* __restrict__ U,
    float* __restrict__ outf, __half* __restrict__ outh,
    __half* __restrict__ outh2, __half* __restrict__ outh3,
    int N, int K, size_t sA, size_t sB, size_t sC)
{
    extern __shared__ char smem[];
    const uint32_t sb = smem_u32(smem);

    const int tid = threadIdx.x, wid = tid >> 5, lane = tid & 31;
    const int m0 = blockIdx.y * 128, n0 = blockIdx.x * 128;

    A += (size_t)blockIdx.z * sA;
    B += (size_t)blockIdx.z * sB;

    const int lrow = tid >> 3;
    const int lu   = tid & 7;
    const int nch = K >> 6;

    const int wm = wid & 3, wn = wid >> 2;
    const int arow = wm * 32 + (lane & 7) + ((lane >> 3) & 1) * 8;
    const int acol = ((lane >> 4) * 8) * 2;
    const int brow = wn * 64 + ((lane >> 4) << 3) + (lane & 7);
    const int bcol = (((lane >> 3) & 1) * 8) * 2;

    float acc[2][8][4];
    #pragma unroll
    for (int i = 0; i < 2; i++)
        #pragma unroll
        for (int j = 0; j < 8; j++)
            #pragma unroll
            for (int t = 0; t < 4; t++) acc[i][j][t] = 0.0f;

    auto issue = [&](int c, int buf) {
        const uint32_t dst = sb + buf * BUFB;
        const size_t kc = (size_t)c * 64;
        #pragma unroll
        for (int j = 0; j < 4; ++j) {
            const int row = lrow + j * 32;
            const size_t ga = (size_t)(m0 + row) * K + kc + lu * 8;
            const size_t gb = (size_t)(n0 + row) * K + kc + lu * 8;
            const uint32_t so = row * TSTRIDE + lu * 16;
            cp16(dst +         so, A + ga);
            cp16(dst + TILEB + so, B + gb);
        }
    };

    issue(0, 0); CP_COMMIT();
    issue(1, 1); CP_COMMIT();

    for (int c = 0; c < nch; ++c) {
        CP_WAIT1();                       // this thread's chunk-c copies done
        __syncthreads();                  // all threads' copies published
        if (c + 2 < nch) issue(c + 2, (c + 2) % 3);
        CP_COMMIT();

        const uint32_t ab = sb + (c % 3) * BUFB;
        const uint32_t bb = ab + TILEB;

        #pragma unroll
        for (int ks = 0; ks < 4; ++ks) {
            const int kb = ks * 32;
            uint32_t af[2][4];
            #pragma unroll
            for (int mf = 0; mf < 2; ++mf)
                ldsm4(af[mf], ab + (arow + mf*16) * TSTRIDE + kb + acol);
            uint32_t bf[8][2];
            #pragma unroll
            for (int g = 0; g < 4; ++g) {
                uint32_t r[4];
                ldsm4(r, bb + (brow + g*16) * TSTRIDE + kb + bcol);
                bf[g*2][0] = r[0];   bf[g*2][1] = r[1];
                bf[g*2+1][0] = r[2]; bf[g*2+1][1] = r[3];
            }
            #pragma unroll
            for (int mf = 0; mf < 2; ++mf)
                #pragma unroll
                for (int nf = 0; nf < 8; ++nf)
                    mma_f16(acc[mf][nf], af[mf], bf[nf]);
        }
    }

    // ---- epilogue
    const int colw = n0 + wn * 64 + (lane & 3) * 2;
    const int roww = m0 + wm * 32 + (lane >> 2);

    const int seg = (EPI == 5) ? (blockIdx.x / 6) : 0;
    const float* bsel = bias;
    __half* osel = outh;
    if (EPI == 5) {
        bsel = (seg == 0) ? bias : (seg == 1 ? bias2 : bias3);
        osel = (seg == 0) ? outh : (seg == 1 ? outh2 : outh3);
    }
    const int csub = (EPI == 5) ? seg * 768 : 0;
    const int NW = (EPI == 5) ? 768 : N;

    #pragma unroll
    for (int mf = 0; mf < 2; ++mf) {
        #pragma unroll
        for (int half = 0; half < 2; ++half) {
            const int row = roww + mf * 16 + half * 8;
            const size_t rb = (size_t)blockIdx.z * sC + (size_t)row * NW;
            // V-transposed store base (seg==2 only)
            const int vb = row >> 10, vs = row & 1023;
            const size_t vbase = (size_t)vb * (768*1024) + vs;
            #pragma unroll
            for (int nf = 0; nf < 8; ++nf) {
                const int col = colw + nf * 8 - csub;
                float v0 = acc[mf][nf][half*2 + 0];
                float v1 = acc[mf][nf][half*2 + 1];

                if (EPI == 2) {
                    const float scale = 0.03608439182435161f;
                    const float2 u = *(const float2*)&U[rb + col];
                    v0 = fmaf(v0, scale, gumbel_f(u.x));
                    v1 = fmaf(v1, scale, gumbel_f(u.y));
                    *(float2*)&outf[rb + col] = make_float2(v0, v1);
                } else if (EPI == 0) {
                    if (bias) { v0 += bias[col]; v1 += bias[col + 1]; }
                    *(float2*)&outf[rb + col] = make_float2(v0, v1);
                } else if (EPI == 3) {
                    v0 = gelu_f(v0 + bias[col]);
                    v1 = gelu_f(v1 + bias[col + 1]);
                    *(uint32_t*)&outh[rb + col] = packh2(v0, v1);
                } else {  // EPI == 5
                    v0 += bsel[col]; v1 += bsel[col + 1];
                    if (seg < 2) {
                        *(uint32_t*)&osel[rb + col] = packh2(v0, v1);
                    } else {
                        // V: write transposed, per-batch [768,1024]
                        osel[vbase + (size_t)col * 1024]       = __float2half_rn(v0);
                        osel[vbase + (size_t)(col + 1) * 1024] = __float2half_rn(v1);
                    }
                }
            }
        }
    }
}

// ---------------------------------------------------------------------------
// elementwise kernels
// ---------------------------------------------------------------------------
__global__ void __launch_bounds__(256) convert_h_k(
    const float4* __restrict__ x, uint2* __restrict__ hi, int n4)
{
    for (int i = blockIdx.x * 256 + threadIdx.x; i < n4; i += gridDim.x * 256) {
        const float4 v = x[i];
        uint2 uh;
        uh.x = packh2(v.x, v.y);
        uh.y = packh2(v.z, v.w);
        hi[i] = uh;
    }
}

// batched QKV weight transpose: z selects wq/wk/wv -> wqkvh + z*DD*DD
__global__ void __launch_bounds__(256) transpose_qkv_k(
    const float* __restrict__ wq, const float* __restrict__ wk,
    const float* __restrict__ wv, __half* __restrict__ oh)
{
    __shared__ float t[32][33];
    const float* in = (blockIdx.z == 0) ? wq : (blockIdx.z == 1 ? wk : wv);
    __half* o = oh + (size_t)blockIdx.z * DD * DD;
    const int bx = blockIdx.x * 32, by = blockIdx.y * 32;
    const int tx = threadIdx.x, ty = threadIdx.y;

    #pragma unroll
    for (int i = ty; i < 32; i += 8)
        t[i][tx] = in[(size_t)(by + i) * DD + bx + tx];
    __syncthreads();
    #pragma unroll
    for (int i = ty; i < 32; i += 8)
        o[(size_t)(bx + i) * DD + by + tx] = __float2half_rn(t[tx][i]);
}

// out[c, r] = fp16(in[r, c])  (fp32 in).  grid(C/32, R/32, batch), block(32,8)
__global__ void __launch_bounds__(256) transpose_h_k(
    const float* __restrict__ in, __half* __restrict__ oh, int R, int C)
{
    __shared__ float t[32][33];
    const size_t boff = (size_t)blockIdx.z * R * C;
    const int bx = blockIdx.x * 32, by = blockIdx.y * 32;
    const int tx = threadIdx.x, ty = threadIdx.y;

    #pragma unroll
    for (int i = ty; i < 32; i += 8)
        t[i][tx] = in[boff + (size_t)(by + i) * C + bx + tx];
    __syncthreads();
    #pragma unroll
    for (int i = ty; i < 32; i += 8) {
        const size_t o = boff + (size_t)(bx + i) * R + by + tx;
        oh[o] = __float2half_rn(t[tx][i]);
    }
}

// softmax over rows of 1024, fp32 in -> fp16 out
__global__ void __launch_bounds__(256) softmax_h_k(
    const float* __restrict__ sc, __half* __restrict__ oh)
{
    __shared__ float red[8];
    const size_t rb = (size_t)blockIdx.x * SS;
    const int tid = threadIdx.x;
    float4 x = ((const float4*)(sc + rb))[tid];

    float m = fmaxf(fmaxf(x.x, x.y), fmaxf(x.z, x.w));
    #pragma unroll
    for (int o = 16; o; o >>= 1) m = fmaxf(m, __shfl_xor_sync(0xffffffffu, m, o));
    if ((tid & 31) == 0) red[tid >> 5] = m;
    __syncthreads();
    float bm = red[0];
    #pragma unroll
    for (int i = 1; i < 8; i++) bm = fmaxf(bm, red[i]);

    x.x = __expf(x.x - bm); x.y = __expf(x.y - bm);
    x.z = __expf(x.z - bm); x.w = __expf(x.w - bm);
    float s = x.x + x.y + x.z + x.w;
    #pragma unroll
    for (int o = 16; o; o >>= 1) s += __shfl_xor_sync(0xffffffffu, s, o);
    __syncthreads();
    if ((tid & 31) == 0) red[tid >> 5] = s;
    __syncthreads();
    float tot = 0.0f;
    #pragma unroll
    for (int i = 0; i < 8; i++) tot += red[i];

    const float inv = 1.0f / tot;
    uint2 uh;
    uh.x = packh2(x.x * inv, x.y * inv);
    uh.y = packh2(x.z * inv, x.w * inv);
    ((uint2*)(oh + rb))[tid] = uh;
}

// out = LN(a + r)*w + b, vectorized: 192 threads, one row, float4 lanes.
template<int TOH>
__global__ void __launch_bounds__(192) add_ln_k(
    const float* __restrict__ a, const float* __restrict__ r,
    const float* __restrict__ w, const float* __restrict__ bb,
    float* __restrict__ out, __half* __restrict__ oh)
{
    __shared__ float rs[6], rq[6];
    const size_t base = (size_t)blockIdx.x * DD;
    const int tid = threadIdx.x;

    const float4 av = ((const float4*)(a + base))[tid];
    const float4 rv = ((const float4*)(r + base))[tid];
    float x0 = av.x + rv.x, x1 = av.y + rv.y, x2 = av.z + rv.z, x3 = av.w + rv.w;

    float s = x0 + x1 + x2 + x3;
    float q = x0*x0 + x1*x1 + x2*x2 + x3*x3;
    #pragma unroll
    for (int o = 16; o; o >>= 1) {
        s += __shfl_xor_sync(0xffffffffu, s, o);
        q += __shfl_xor_sync(0xffffffffu, q, o);
    }
    if ((tid & 31) == 0) { rs[tid >> 5] = s; rq[tid >> 5] = q; }
    __syncthreads();
    float S_ = 0.0f, Q_ = 0.0f;
    #pragma unroll
    for (int i = 0; i < 6; i++) { S_ += rs[i]; Q_ += rq[i]; }

    const float invD = 1.0f / 768.0f;
    const float mean = S_ * invD;
    const float var  = Q_ * invD - mean * mean;
    const float inv  = rsqrtf(var + 1e-5f);

    const float4 wv = ((const float4*)w)[tid];
    const float4 bv = ((const float4*)bb)[tid];
    float4 o;
    o.x = (x0 - mean) * inv * wv.x + bv.x;
    o.y = (x1 - mean) * inv * wv.y + bv.y;
    o.z = (x2 - mean) * inv * wv.z + bv.z;
    o.w = (x3 - mean) * inv * wv.w + bv.w;
    ((float4*)(out + base))[tid] = o;
    if (TOH) {
        uint2 uh;
        uh.x = packh2(o.x, o.y);
        uh.y = packh2(o.z, o.w);
        ((uint2*)(oh + base))[tid] = uh;
    }
}

// ---------------------------------------------------------------------------
extern "C" void kernel_launch(void* const* d_in, const int* in_sizes, int n_in,
                              void* d_out, int out_size)
{
    const float* src  = (const float*)d_in[0];
    const float* gu   = (const float*)d_in[1];
    const float* wq   = (const float*)d_in[2];
    const float* bq   = (const float*)d_in[3];
    const float* wk   = (const float*)d_in[4];
    const float* bk   = (const float*)d_in[5];
    const float* wv   = (const float*)d_in[6];
    const float* bv   = (const float*)d_in[7];
    const float* w1   = (const float*)d_in[8];
    const float* b1   = (const float*)d_in[9];
    const float* w2   = (const float*)d_in[10];
    const float* b2   = (const float*)d_in[11];
    const float* ln1w = (const float*)d_in[12];
    const float* ln1b = (const float*)d_in[13];
    const float* ln2w = (const float*)d_in[14];
    const float* ln2b = (const float*)d_in[15];
    float* out = (float*)d_out;

    cudaFuncSetAttribute(gemm_mma<0>, cudaFuncAttributeMaxDynamicSharedMemorySize, GSMEM);
    cudaFuncSetAttribute(gemm_mma<2>, cudaFuncAttributeMaxDynamicSharedMemorySize, GSMEM);
    cudaFuncSetAttribute(gemm_mma<3>, cudaFuncAttributeMaxDynamicSharedMemorySize, GSMEM);
    cudaFuncSetAttribute(gemm_mma<5>, cudaFuncAttributeMaxDynamicSharedMemorySize, GSMEM);

    __half *srch, *wqkvh, *w1h, *w2h;
    __half *qh, *kh, *vth, *ah, *xh, *hh;
    float *v, *scores, *x;
    cudaGetSymbolAddress((void**)&srch, g_srch);
    cudaGetSymbolAddress((void**)&wqkvh, g_wqkvh);
    cudaGetSymbolAddress((void**)&w1h, g_w1h);
    cudaGetSymbolAddress((void**)&w2h, g_w2h);
    cudaGetSymbolAddress((void**)&qh, g_qh);
    cudaGetSymbolAddress((void**)&kh, g_kh);
    cudaGetSymbolAddress((void**)&vth, g_vth);
    cudaGetSymbolAddress((void**)&v, g_v);
    cudaGetSymbolAddress((void**)&scores, g_scores);
    cudaGetSymbolAddress((void**)&ah, g_ah);
    cudaGetSymbolAddress((void**)&x, g_x);
    cudaGetSymbolAddress((void**)&xh, g_xh);
    cudaGetSymbolAddress((void**)&hh, g_hh);

    const size_t sSD = (size_t)SS * DD;
    const size_t sSS = (size_t)SS * SS;
    const size_t hSD = (size_t)MHALF * DD;
    const size_t hFF = (size_t)MHALF * DFFN;
    const int n4h = MTOT*DD/8;

    // ---- fork root ---------------------------------------------------------
    cudaEventRecord(g_eRoot, 0);
    cudaStreamWaitEvent(g_s1, g_eRoot, 0);
    cudaStreamWaitEvent(g_s3, g_eRoot, 0);
    cudaStreamWaitEvent(g_s4, g_eRoot, 0);
    cudaStreamWaitEvent(g_s5, g_eRoot, 0);

    // launch 0,1 (main): src -> fp16, in halves
    convert_h_k<<<6144, 256>>>((const float4*)src, (uint2*)srch, n4h);
    convert_h_k<<<6144, 256>>>((const float4*)(src + hSD), (uint2*)(srch + hSD), n4h);

    // launch 2 (s1): batched QKV weight transpose
    transpose_qkv_k<<<dim3(24, 24, 3), dim3(32, 8), 0, g_s1>>>(wq, wk, wv, wqkvh);
    cudaEventRecord(g_eW, g_s1);

    // launch 3 (main, ncu-profiled): fused QKV projection, half 1
    cudaStreamWaitEvent(0, g_eW, 0);
    gemm_mma<5><<<dim3(18, 64, 1), 256, GSMEM>>>(srch, wqkvh, bq, bk, bv, nullptr,
        nullptr, qh, kh, vth, 3*DD, DD, 0, 0, 0);
    cudaEventRecord(g_eQ1, 0);
    // QKV half 2
    gemm_mma<5><<<dim3(18, 64, 1), 256, GSMEM>>>(srch + hSD, wqkvh, bq, bk, bv, nullptr,
        nullptr, qh + hSD, kh + hSD, vth + hSD, 3*DD, DD, 0, 0, 0);
    cudaEventRecord(g_eQ2, 0);

    // s3: FFN weight transposes
    transpose_h_k<<<dim3(96, 24, 1), dim3(32, 8), 0, g_s3>>>(w1, w1h, DD, DFFN);
    transpose_h_k<<<dim3(24, 96, 1), dim3(32, 8), 0, g_s3>>>(w2, w2h, DFFN, DD);
    cudaEventRecord(g_eW12, g_s3);

    // ---- half-pipeline 1 on s4 (batches 0:8 / rows 0:8192) -----------------
    cudaStreamWaitEvent(g_s4, g_eQ1, 0);
    gemm_mma<2><<<dim3(8, 8, BH), 256, GSMEM, g_s4>>>(qh, kh, nullptr, nullptr, nullptr, gu,
        scores, nullptr, nullptr, nullptr, SS, DD, sSD, sSD, sSS);
    softmax_h_k<<<BH*SS, 256, 0, g_s4>>>(scores, ah);
    gemm_mma<0><<<dim3(6, 8, BH), 256, GSMEM, g_s4>>>(ah, vth, nullptr, nullptr, nullptr, nullptr,
        v, nullptr, nullptr, nullptr, DD, SS, sSS, sSD, sSD);
    add_ln_k<1><<<MHALF, 192, 0, g_s4>>>(src, v, ln1w, ln1b, x, xh);
    cudaStreamWaitEvent(g_s4, g_eW12, 0);
    gemm_mma<3><<<dim3(24, 64, 1), 256, GSMEM, g_s4>>>(xh, w1h, b1, nullptr, nullptr, nullptr,
        nullptr, hh, nullptr, nullptr, DFFN, DD, 0, 0, 0);
    gemm_mma<0><<<dim3(6, 64, 1), 256, GSMEM, g_s4>>>(hh, w2h, b2, nullptr, nullptr, nullptr,
        scores, nullptr, nullptr, nullptr, DD, DFFN, 0, 0, 0);
    add_ln_k<0><<<MHALF, 192, 0, g_s4>>>(x, scores, ln2w, ln2b, out, nullptr);
    cudaEventRecord(g_eD1, g_s4);

    // ---- half-pipeline 2 on s5 (batches 8:16 / rows 8192:16384) ------------
    float* ff2 = scores + BH*sSS;   // own half's scores region (disjoint from h1 writes)
    cudaStreamWaitEvent(g_s5, g_eQ2, 0);
    gemm_mma<2><<<dim3(8, 8, BH), 256, GSMEM, g_s5>>>(qh + BH*sSD, kh + BH*sSD,
        nullptr, nullptr, nullptr, gu + BH*sSS,
        scores + BH*sSS, nullptr, nullptr, nullptr, SS, DD, sSD, sSD, sSS);
    softmax_h_k<<<BH*SS, 256, 0, g_s5>>>(scores + BH*sSS, ah + BH*sSS);
    gemm_mma<0><<<dim3(6, 8, BH), 256, GSMEM, g_s5>>>(ah + BH*sSS, vth + BH*sSD,
        nullptr, nullptr, nullptr, nullptr,
        v + BH*sSD, nullptr, nullptr, nullptr, DD, SS, sSS, sSD, sSD);
    add_ln_k<1><<<MHALF, 192, 0, g_s5>>>(src + hSD, v + hSD, ln1w, ln1b, x + hSD, xh + hSD);
    cudaStreamWaitEvent(g_s5, g_eW12, 0);
    gemm_mma<3><<<dim3(24, 64, 1), 256, GSMEM, g_s5>>>(xh + hSD, w1h, b1, nullptr, nullptr, nullptr,
        nullptr, hh + hFF, nullptr, nullptr, DFFN, DD, 0, 0, 0);
    gemm_mma<0><<<dim3(6, 64, 1), 256, GSMEM, g_s5>>>(hh + hFF, w2h, b2, nullptr, nullptr, nullptr,
        ff2, nullptr, nullptr, nullptr, DD, DFFN, 0, 0, 0);
    add_ln_k<0><<<MHALF, 192, 0, g_s5>>>(x + hSD, ff2, ln2w, ln2b, out + hSD, nullptr);
    cudaEventRecord(g_eD2, g_s5);

    // join
    cudaStreamWaitEvent(0, g_eD1, 0);
    cudaStreamWaitEvent(0, g_eD2, 0);
}